// round 14
// baseline (speedup 1.0000x reference)
#include <cuda_runtime.h>

#define BATCH 64
#define KPTS  2048
#define NTHR  512
#define G     96
#define NCELL (G * G)               // 9216 cells
#define CPT   (NCELL / NTHR)        // 18 cells per thread
#define QPT   (KPTS / NTHR)         // 4 points per thread
#define XMIN  (-5.2f)
#define SPAN  (10.4f)
#define NBLK  (2 * BATCH)           // 128 blocks: (dir, batch)
#define INF_BITS 0x7f800000

// dynamic smem byte offsets
#define CNT_OFF 0                                   // int cnt[NCELL]
#define CST_OFF (NCELL * 4)                         // int cst[NCELL+1]
#define PTS_OFF ((CST_OFF + (NCELL + 1) * 4 + 15) & ~15)  // float2 pts[KPTS]
#define RED_OFF (PTS_OFF + KPTS * 8)                // float red[NTHR]
#define SMEM_SZ (RED_OFF + NTHR * 4)                // ~92.2 KB

__device__ float g_part[NBLK];
__device__ unsigned int g_ticket;    // zero-init; last block resets

extern __shared__ char smem_dyn[];

__global__ void __launch_bounds__(NTHR)
chamfer_binned(const float* __restrict__ P, const float* __restrict__ T,
               float* __restrict__ out) {
    int*    cnt = (int*)(smem_dyn + CNT_OFF);
    int*    cst = (int*)(smem_dyn + CST_OFF);
    float2* pts = (float2*)(smem_dyn + PTS_OFF);
    float*  red = (float*)(smem_dyn + RED_OFF);
    int*    scn = (int*)red;                 // scan scratch (reused later)
    __shared__ bool amLast;

    const int dir = blockIdx.x & 1;          // 0: bin T / query P ; 1: swapped
    const int b   = blockIdx.x >> 1;
    const int tid = threadIdx.x;

    const float* Bp = (dir ? P : T) + b * (2 * KPTS);  // binned side
    const float* Qp = (dir ? T : P) + b * (2 * KPTS);  // query side

    const float invw = (float)G / SPAN;
    const float w    = SPAN / (float)G;

    // ---- zero counters ----
#pragma unroll
    for (int k = 0; k < CPT; ++k) cnt[tid + k * NTHR] = 0;
    __syncthreads();

    // ---- load bin-side points, count cells ----
    float bx[QPT], by[QPT]; int bc[QPT];
#pragma unroll
    for (int k = 0; k < QPT; ++k) {
        int i = tid + k * NTHR;
        float x = Bp[i], y = Bp[KPTS + i];
        int cx = min(G - 1, max(0, (int)((x - XMIN) * invw)));
        int cy = min(G - 1, max(0, (int)((y - XMIN) * invw)));
        bx[k] = x; by[k] = y; bc[k] = cy * G + cx;
        atomicAdd(&cnt[bc[k]], 1);
    }
    __syncthreads();

    // ---- exclusive prefix over cells (per-thread sums + block scan) ----
    const int base = tid * CPT;
    int s = 0;
#pragma unroll
    for (int k = 0; k < CPT; ++k) s += cnt[base + k];
    scn[tid] = s;
    __syncthreads();
    for (int off = 1; off < NTHR; off <<= 1) {
        int v = scn[tid];
        if (tid >= off) v += scn[tid - off];
        __syncthreads();
        scn[tid] = v;
        __syncthreads();
    }
    int run = scn[tid] - s;                  // exclusive base for my cell range
    __syncthreads();
#pragma unroll
    for (int k = 0; k < CPT; ++k) {
        int c = base + k;
        cst[c] = run;
        run += cnt[c];
    }
    if (tid == NTHR - 1) cst[NCELL] = KPTS;
    __syncthreads();

    // ---- cursors = starts; scatter (counting sort by cell) ----
#pragma unroll
    for (int k = 0; k < CPT; ++k) cnt[base + k] = cst[base + k];
    __syncthreads();
#pragma unroll
    for (int k = 0; k < QPT; ++k) {
        int pos = atomicAdd(&cnt[bc[k]], 1);
        pts[pos] = make_float2(bx[k], by[k]);
    }
    __syncthreads();

    // ---- query phase: exact NN via ring-expanding grid search ----
    float acc = 0.0f;
    for (int k = 0; k < QPT; ++k) {
        int i = tid + k * NTHR;
        float qx = Qp[i], qy = Qp[KPTS + i];
        int cx = min(G - 1, max(0, (int)((qx - XMIN) * invw)));
        int cy = min(G - 1, max(0, (int)((qy - XMIN) * invw)));
        float best = __int_as_float(INF_BITS);

        // scan cells [xl..xh] in row y (contiguous point run after sort)
        auto scan_row = [&](int y, int xl, int xh) {
            if (y < 0 || y >= G) return;
            xl = max(xl, 0); xh = min(xh, G - 1);
            if (xl > xh) return;
            int s0 = cst[y * G + xl];
            int e0 = cst[y * G + xh + 1];
            for (int t = s0; t < e0; ++t) {
                float2 p = pts[t];
                float dx = qx - p.x, dy = qy - p.y;
                float d2 = fmaf(dx, dx, dy * dy);
                best = fminf(best, d2);
            }
        };

        // initial square: Chebyshev radius 1 (3 contiguous row runs)
        scan_row(cy - 1, cx - 1, cx + 1);
        scan_row(cy,     cx - 1, cx + 1);
        scan_row(cy + 1, cx - 1, cx + 1);

        for (int r = 1; ; ++r) {
            // min possible distance from q to any UNSEARCHED cell region.
            // Clipped sides have no points beyond them -> infinite.
            float dL = (cx - r <= 0)     ? 1e30f : qx - (XMIN + (float)(cx - r) * w);
            float dR = (cx + r >= G - 1) ? 1e30f : (XMIN + (float)(cx + r + 1) * w) - qx;
            float dB = (cy - r <= 0)     ? 1e30f : qy - (XMIN + (float)(cy - r) * w);
            float dT = (cy + r >= G - 1) ? 1e30f : (XMIN + (float)(cy + r + 1) * w) - qy;
            float dE = fminf(fminf(dL, dR), fminf(dB, dT));
            if (dE > 0.0f && best <= dE * dE) break;   // exact: nothing closer outside
            if (dE >= 1e29f) break;                    // whole grid searched
            // expand: scan ring at radius r+1
            int rn = r + 1;
            scan_row(cy - rn, cx - rn, cx + rn);
            scan_row(cy + rn, cx - rn, cx + rn);
            for (int yy = cy - rn + 1; yy <= cy + rn - 1; ++yy) {
                scan_row(yy, cx - rn, cx - rn);
                scan_row(yy, cx + rn, cx + rn);
            }
        }
        acc += sqrtf(best);     // best >= 0 by construction (difference form)
    }

    // ---- block reduction ----
    red[tid] = acc;
    __syncthreads();
#pragma unroll
    for (int st = NTHR / 2; st > 0; st >>= 1) {
        if (tid < st) red[tid] += red[tid + st];
        __syncthreads();
    }

    // ---- ticketed final sum over 128 block partials ----
    if (tid == 0) {
        g_part[blockIdx.x] = red[0];
        __threadfence();
        unsigned int t = atomicAdd(&g_ticket, 1u);
        amLast = (t == NBLK - 1);
    }
    __syncthreads();
    if (!amLast) return;

    __threadfence();
    red[tid] = (tid < NBLK) ? g_part[tid] : 0.0f;
    __syncthreads();
#pragma unroll
    for (int st = NTHR / 2; st > 0; st >>= 1) {
        if (tid < st) red[tid] += red[tid + st];
        __syncthreads();
    }
    if (tid == 0) {
        out[0] = red[0] * (1.0f / (float)(BATCH * KPTS));
        g_ticket = 0;                        // reset for next graph replay
    }
}

extern "C" void kernel_launch(void* const* d_in, const int* in_sizes, int n_in,
                              void* d_out, int out_size) {
    const float* P = (const float*)d_in[0];   // predicted (64, 4096)
    const float* T = (const float*)d_in[1];   // target    (64, 4096)
    (void)in_sizes; (void)n_in; (void)out_size;

    // >48KB dynamic smem requires opt-in (idempotent; not a stream op)
    cudaFuncSetAttribute(chamfer_binned,
                         cudaFuncAttributeMaxDynamicSharedMemorySize, SMEM_SZ);
    chamfer_binned<<<NBLK, NTHR, SMEM_SZ>>>(P, T, (float*)d_out);
}

// round 16
// speedup vs baseline: 1.1879x; 1.1879x over previous
#include <cuda_runtime.h>

#define BATCH 64
#define KPTS  2048
#define NTHR  512
#define QS    4                     // query-split: blocks per (dir, batch)
#define G     96
#define NCELL (G * G)               // 9216 cells
#define CPT   (NCELL / NTHR)        // 18 cells per thread
#define BPT   (KPTS / NTHR)         // 4 bin-side points per thread
#define XMIN  (-5.2f)
#define SPAN  (10.4f)
#define NBLK  (QS * 2 * BATCH)      // 512 blocks
#define INF_BITS 0x7f800000

// dynamic smem byte offsets
#define CNT_OFF 0                                   // int cnt[NCELL]
#define CST_OFF (NCELL * 4)                         // int cst[NCELL+1]
#define PTS_OFF ((CST_OFF + (NCELL + 1) * 4 + 15) & ~15)  // float2 pts[KPTS]
#define RED_OFF (PTS_OFF + KPTS * 8)                // float red[NTHR]
#define SMEM_SZ (RED_OFF + NTHR * 4)                // ~92.2 KB

__device__ float g_part[NBLK];
__device__ unsigned int g_ticket;    // zero-init; last block resets

extern __shared__ char smem_dyn[];

__global__ void __launch_bounds__(NTHR)
chamfer_binned(const float* __restrict__ P, const float* __restrict__ T,
               float* __restrict__ out) {
    int*    cnt = (int*)(smem_dyn + CNT_OFF);
    int*    cst = (int*)(smem_dyn + CST_OFF);
    float2* pts = (float2*)(smem_dyn + PTS_OFF);
    float*  red = (float*)(smem_dyn + RED_OFF);
    int*    scn = (int*)red;                 // scan scratch (reused later)
    __shared__ bool amLast;

    const int qs  = blockIdx.x;              // query chunk within (dir, b)
    const int dir = blockIdx.y;              // 0: bin T / query P ; 1: swapped
    const int b   = blockIdx.z;
    const int tid = threadIdx.x;

    const float* Bp = (dir ? P : T) + b * (2 * KPTS);  // binned side
    const float* Qp = (dir ? T : P) + b * (2 * KPTS);  // query side

    const float invw = (float)G / SPAN;
    const float w    = SPAN / (float)G;

    // ---- zero counters ----
#pragma unroll
    for (int k = 0; k < CPT; ++k) cnt[tid + k * NTHR] = 0;
    __syncthreads();

    // ---- load bin-side points, count cells (redundant per qs-chunk; cheap) ----
    float bx[BPT], by[BPT]; int bc[BPT];
#pragma unroll
    for (int k = 0; k < BPT; ++k) {
        int i = tid + k * NTHR;
        float x = Bp[i], y = Bp[KPTS + i];
        int cx = min(G - 1, max(0, (int)((x - XMIN) * invw)));
        int cy = min(G - 1, max(0, (int)((y - XMIN) * invw)));
        bx[k] = x; by[k] = y; bc[k] = cy * G + cx;
        atomicAdd(&cnt[bc[k]], 1);
    }
    __syncthreads();

    // ---- exclusive prefix over cells (per-thread sums + block scan) ----
    const int base = tid * CPT;
    int s = 0;
#pragma unroll
    for (int k = 0; k < CPT; ++k) s += cnt[base + k];
    scn[tid] = s;
    __syncthreads();
    for (int off = 1; off < NTHR; off <<= 1) {
        int v = scn[tid];
        if (tid >= off) v += scn[tid - off];
        __syncthreads();
        scn[tid] = v;
        __syncthreads();
    }
    int run = scn[tid] - s;                  // exclusive base for my cell range
    __syncthreads();
#pragma unroll
    for (int k = 0; k < CPT; ++k) {
        int c = base + k;
        cst[c] = run;
        run += cnt[c];
    }
    if (tid == NTHR - 1) cst[NCELL] = KPTS;
    __syncthreads();

    // ---- cursors = starts; scatter (counting sort by cell) ----
#pragma unroll
    for (int k = 0; k < CPT; ++k) cnt[base + k] = cst[base + k];
    __syncthreads();
#pragma unroll
    for (int k = 0; k < BPT; ++k) {
        int pos = atomicAdd(&cnt[bc[k]], 1);
        pts[pos] = make_float2(bx[k], by[k]);
    }
    __syncthreads();

    // ---- query phase: ONE query per thread (this block's 512-query chunk) ----
    float acc = 0.0f;
    {
        const int i = qs * NTHR + tid;
        float qx = Qp[i], qy = Qp[KPTS + i];
        int cx = min(G - 1, max(0, (int)((qx - XMIN) * invw)));
        int cy = min(G - 1, max(0, (int)((qy - XMIN) * invw)));
        float best = __int_as_float(INF_BITS);

        // scan cells [xl..xh] in row y (contiguous point run after sort)
        auto scan_row = [&](int y, int xl, int xh) {
            if (y < 0 || y >= G) return;
            xl = max(xl, 0); xh = min(xh, G - 1);
            if (xl > xh) return;
            int s0 = cst[y * G + xl];
            int e0 = cst[y * G + xh + 1];
            for (int t = s0; t < e0; ++t) {
                float2 p = pts[t];
                float dx = qx - p.x, dy = qy - p.y;
                float d2 = fmaf(dx, dx, dy * dy);
                best = fminf(best, d2);
            }
        };

        // initial square: Chebyshev radius 1 (3 contiguous row runs)
        scan_row(cy - 1, cx - 1, cx + 1);
        scan_row(cy,     cx - 1, cx + 1);
        scan_row(cy + 1, cx - 1, cx + 1);

        for (int r = 1; ; ++r) {
            // min possible distance from q to any UNSEARCHED cell region.
            // Clipped sides have no points beyond them -> infinite.
            float dL = (cx - r <= 0)     ? 1e30f : qx - (XMIN + (float)(cx - r) * w);
            float dR = (cx + r >= G - 1) ? 1e30f : (XMIN + (float)(cx + r + 1) * w) - qx;
            float dB = (cy - r <= 0)     ? 1e30f : qy - (XMIN + (float)(cy - r) * w);
            float dT = (cy + r >= G - 1) ? 1e30f : (XMIN + (float)(cy + r + 1) * w) - qy;
            float dE = fminf(fminf(dL, dR), fminf(dB, dT));
            if (dE > 0.0f && best <= dE * dE) break;   // exact: nothing closer outside
            if (dE >= 1e29f) break;                    // whole grid searched
            // expand: scan ring at radius r+1
            int rn = r + 1;
            scan_row(cy - rn, cx - rn, cx + rn);
            scan_row(cy + rn, cx - rn, cx + rn);
            for (int yy = cy - rn + 1; yy <= cy + rn - 1; ++yy) {
                scan_row(yy, cx - rn, cx - rn);
                scan_row(yy, cx + rn, cx + rn);
            }
        }
        acc = sqrtf(best);      // best >= 0 by construction (difference form)
    }

    // ---- block reduction ----
    red[tid] = acc;
    __syncthreads();
#pragma unroll
    for (int st = NTHR / 2; st > 0; st >>= 1) {
        if (tid < st) red[tid] += red[tid + st];
        __syncthreads();
    }

    // ---- ticketed final sum over 512 block partials ----
    const int bid = qs + QS * (dir + 2 * b);
    if (tid == 0) {
        g_part[bid] = red[0];
        __threadfence();
        unsigned int t = atomicAdd(&g_ticket, 1u);
        amLast = (t == NBLK - 1);
    }
    __syncthreads();
    if (!amLast) return;

    __threadfence();
    red[tid] = g_part[tid];                  // NTHR == NBLK == 512
    __syncthreads();
#pragma unroll
    for (int st = NTHR / 2; st > 0; st >>= 1) {
        if (tid < st) red[tid] += red[tid + st];
        __syncthreads();
    }
    if (tid == 0) {
        out[0] = red[0] * (1.0f / (float)(BATCH * KPTS));
        g_ticket = 0;                        // reset for next graph replay
    }
}

extern "C" void kernel_launch(void* const* d_in, const int* in_sizes, int n_in,
                              void* d_out, int out_size) {
    const float* P = (const float*)d_in[0];   // predicted (64, 4096)
    const float* T = (const float*)d_in[1];   // target    (64, 4096)
    (void)in_sizes; (void)n_in; (void)out_size;

    // >48KB dynamic smem requires opt-in (idempotent; not a stream op)
    cudaFuncSetAttribute(chamfer_binned,
                         cudaFuncAttributeMaxDynamicSharedMemorySize, SMEM_SZ);
    dim3 grid(QS, 2, BATCH);                  // 4 x 2 x 64 = 512 blocks
    chamfer_binned<<<grid, NTHR, SMEM_SZ>>>(P, T, (float*)d_out);
}